// round 14
// baseline (speedup 1.0000x reference)
#include <cuda_runtime.h>
#include <cuda_bf16.h>
#include <cstdint>
#include <math.h>

#define C_CLS 1000
#define CP    1024
#define AD    512
#define HD    256
#define NMAX  131072
#define KCHH  64
#define SSTRH 72
#define GRID_MAIN 128
#define GSMEM ((2*128*SSTRH + 2*64*SSTRH) * 2)   // 55296 bytes

// ---------------- scratch ----------------------------------------------------
__device__ __nv_bfloat16 g_attr_bf[CP * AD];
__device__ __nv_bfloat16 g_p_bf[CP * HD];
__device__ __nv_bfloat16 g_q_bf[CP * HD];
__device__ __nv_bfloat16 g_enc_bf[CP * AD];
__device__ __nv_bfloat16 g_hT_bf[HD * AD];
__device__ __nv_bfloat16 g_gT_bf[HD * AD];
__device__ float g_G[CP * CP];
__device__ float g_meanp[4 * C_CLS * AD];
__device__ float g_invn[CP];
__device__ int   g_counts[C_CLS];
__device__ int   g_offsets[C_CLS];
__device__ int   g_cursor[C_CLS];
__device__ int   g_sorted[NMAX];
__device__ int   g_done = 0;
__device__ int   g_pdone = 0;
__device__ int   g_barc = 0;
__device__ volatile int g_barg = 0;

// ---------------- helpers ----------------------------------------------------
__device__ __forceinline__ float warpSum(float v) {
#pragma unroll
    for (int o = 16; o; o >>= 1) v += __shfl_xor_sync(0xffffffffu, v, o);
    return v;
}
__device__ __forceinline__ float warpMax(float v) {
#pragma unroll
    for (int o = 16; o; o >>= 1) v = fmaxf(v, __shfl_xor_sync(0xffffffffu, v, o));
    return v;
}
__device__ __forceinline__ float blockSum(float v, float* sh) {
    int t = threadIdx.x, lane = t & 31, w = t >> 5, nw = blockDim.x >> 5;
    v = warpSum(v);
    if (!lane) sh[w] = v;
    __syncthreads();
    if (w == 0) {
        float x = (lane < nw) ? sh[lane] : 0.f;
        x = warpSum(x);
        if (!lane) sh[0] = x;
    }
    __syncthreads();
    float r = sh[0];
    __syncthreads();
    return r;
}
__device__ __forceinline__ float blockMax(float v, float* sh) {
    int t = threadIdx.x, lane = t & 31, w = t >> 5, nw = blockDim.x >> 5;
    v = warpMax(v);
    if (!lane) sh[w] = v;
    __syncthreads();
    if (w == 0) {
        float x = (lane < nw) ? sh[lane] : -1e30f;
        x = warpMax(x);
        if (!lane) sh[0] = x;
    }
    __syncthreads();
    float r = sh[0];
    __syncthreads();
    return r;
}
__device__ __forceinline__ void cp16(uint32_t dst, const void* src) {
    asm volatile("cp.async.ca.shared.global [%0], [%1], 16;" :: "r"(dst), "l"(src));
}
__device__ __forceinline__ uint32_t bf2pack(float a, float b) {
    __nv_bfloat162 h = __floats2bfloat162_rn(a, b);
    return *(uint32_t*)&h;
}
__device__ __forceinline__ void mma_bf16(float* c, const uint32_t* a, const uint32_t* b) {
    asm volatile(
        "mma.sync.aligned.m16n8k16.row.col.f32.bf16.bf16.f32 "
        "{%0,%1,%2,%3}, {%4,%5,%6,%7}, {%8,%9}, {%0,%1,%2,%3};"
        : "+f"(c[0]), "+f"(c[1]), "+f"(c[2]), "+f"(c[3])
        : "r"(a[0]), "r"(a[1]), "r"(a[2]), "r"(a[3]), "r"(b[0]), "r"(b[1]));
}
__device__ __forceinline__ void gridbar() {
    __syncthreads();
    if (threadIdx.x == 0) {
        __threadfence();
        int gen = g_barg;
        if (atomicAdd(&g_barc, 1) == GRID_MAIN - 1) {
            g_barc = 0;
            __threadfence();
            g_barg = gen + 1;
        } else {
            while (g_barg == gen) { }
        }
    }
    __syncthreads();
}

// ------- fused hist + scan (last-block pattern) ------------------------------
#define HIST_BLOCKS 25
__global__ __launch_bounds__(256) void hist_scan_k(const int* __restrict__ labels, int n) {
    __shared__ int h[C_CLS];
    __shared__ int amLast;
    const int tid = threadIdx.x;
    for (int i = tid; i < C_CLS; i += 256) h[i] = 0;
    __syncthreads();
    for (int i = blockIdx.x * blockDim.x + tid; i < n; i += gridDim.x * blockDim.x)
        atomicAdd(&h[labels[i]], 1);
    __syncthreads();
    for (int i = tid; i < C_CLS; i += 256)
        if (h[i]) atomicAdd(&g_counts[i], h[i]);
    __threadfence();
    if (tid == 0) amLast = (atomicAdd(&g_done, 1) == HIST_BLOCKS - 1);
    __syncthreads();
    if (amLast && tid < 32) {
        int lane = tid;
        int base = lane * 32;
        int loc[32];
        int s = 0;
#pragma unroll
        for (int j = 0; j < 32; j++) {
            int idx = base + j;
            int c = (idx < C_CLS) ? g_counts[idx] : 0;
            loc[j] = s;
            s += c;
        }
        int inc = s;
#pragma unroll
        for (int o = 1; o < 32; o <<= 1) {
            int nv = __shfl_up_sync(0xffffffffu, inc, o);
            if (lane >= o) inc += nv;
        }
        int excl = inc - s;
#pragma unroll
        for (int j = 0; j < 32; j++) {
            int idx = base + j;
            if (idx < C_CLS) g_offsets[idx] = excl + loc[j];
        }
        if (lane == 0) g_done = 0;
    }
}
__global__ __launch_bounds__(256) void scatter_k(const int* __restrict__ labels, int n) {
    int i0 = (blockIdx.x * blockDim.x + threadIdx.x) * 4;
    int l[4], pos[4];
#pragma unroll
    for (int j = 0; j < 4; j++) {
        int i = i0 + j;
        if (i < n) {
            l[j] = labels[i];
            pos[j] = atomicAdd(&g_cursor[l[j]], 1);
        } else l[j] = -1;
    }
#pragma unroll
    for (int j = 0; j < 4; j++)
        if (l[j] >= 0) g_sorted[g_offsets[l[j]] + pos[j]] = i0 + j;
}
// ---- class partial sums: 4 CTAs/class, 256 threads (2 row-groups x 128 cols)
__global__ __launch_bounds__(256) void class_mean4_k(const float* __restrict__ img) {
    int c = blockIdx.x >> 2, q = blockIdx.x & 3;
    int t = threadIdx.x;
    int col = t & 127, rg = t >> 7;   // row-group 0/1
    int cnt = g_counts[c], off = g_offsets[c];
    int lo = (cnt * q) >> 2, hi = (cnt * (q + 1)) >> 2;
    int len = hi - lo;
    __shared__ int idx[128];
    __shared__ float4 red[128];
    int lim = len < 128 ? len : 128;
    for (int j = t; j < lim; j += 256) idx[j] = g_sorted[off + lo + j];
    __syncthreads();
    float4 acc = make_float4(0.f, 0.f, 0.f, 0.f);
    int j = rg;
    for (; j + 6 < lim; j += 8) {
        float4 a = ((const float4*)(img + (size_t)idx[j] * AD))[col];
        float4 b = ((const float4*)(img + (size_t)idx[j + 2] * AD))[col];
        float4 d = ((const float4*)(img + (size_t)idx[j + 4] * AD))[col];
        float4 e = ((const float4*)(img + (size_t)idx[j + 6] * AD))[col];
        acc.x += a.x + b.x + d.x + e.x;
        acc.y += a.y + b.y + d.y + e.y;
        acc.z += a.z + b.z + d.z + e.z;
        acc.w += a.w + b.w + d.w + e.w;
    }
    for (; j < lim; j += 2) {
        float4 a = ((const float4*)(img + (size_t)idx[j] * AD))[col];
        acc.x += a.x; acc.y += a.y; acc.z += a.z; acc.w += a.w;
    }
    for (j = lim + rg; j < len; j += 2) {   // rare tail (>128 rows per quarter)
        float4 a = ((const float4*)(img + (size_t)g_sorted[off + lo + j] * AD))[col];
        acc.x += a.x; acc.y += a.y; acc.z += a.z; acc.w += a.w;
    }
    if (rg == 1) red[col] = acc;
    __syncthreads();
    if (rg == 0) {
        float4 o2 = red[col];
        acc.x += o2.x; acc.y += o2.y; acc.z += o2.z; acc.w += o2.w;
        ((float4*)(g_meanp + (size_t)blockIdx.x * AD))[col] = acc;
    }
    __threadfence();
    __syncthreads();
    if (t == 0) atomicAdd(&g_pdone, 1);
}

// ------ GEMM variant A: 128x64 tile, fp32 out (+optional diag) ---------------
__device__ __noinline__ void gemm_phase(const __nv_bfloat16* A, const __nv_bfloat16* B,
                                        float* dst, int N, int K, int nch,
                                        int m0, int n0, int diagflag,
                                        __nv_bfloat16* smh) {
    const int tid = threadIdx.x, wid = tid >> 5, lane = tid & 31;
    const int gid = lane >> 2, tig = lane & 3;
    const int wm = (wid & 3) * 32, wn = (wid >> 2) * 32;
    const uint32_t sbase = (uint32_t)__cvta_generic_to_shared(smh);
    const uint32_t* Asm = (const uint32_t*)smh;
    const uint32_t* Bsm = (const uint32_t*)(smh + 2 * 128 * SSTRH);

    float acc[2][4][4];
#pragma unroll
    for (int a = 0; a < 2; a++)
#pragma unroll
        for (int b = 0; b < 4; b++)
#pragma unroll
            for (int c = 0; c < 4; c++) acc[a][b][c] = 0.f;

    auto loadc = [&](int kc, int buf) {
        const __nv_bfloat16* Ab = A + (size_t)m0 * K + kc * KCHH;
        const __nv_bfloat16* Bb = B + (size_t)n0 * K + kc * KCHH;
        uint32_t as0 = sbase + (uint32_t)(buf * 128 * SSTRH) * 2u;
        uint32_t bs0 = sbase + (uint32_t)(2 * 128 * SSTRH + buf * 64 * SSTRH) * 2u;
#pragma unroll
        for (int i = 0; i < 4; i++) {
            int idx = tid + i * 256;
            int row = idx >> 3, kq = (idx & 7) * 8;
            cp16(as0 + (uint32_t)(row * SSTRH + kq) * 2u, Ab + (size_t)row * K + kq);
        }
#pragma unroll
        for (int i = 0; i < 2; i++) {
            int idx = tid + i * 256;
            int row = idx >> 3, kq = (idx & 7) * 8;
            cp16(bs0 + (uint32_t)(row * SSTRH + kq) * 2u, Bb + (size_t)row * K + kq);
        }
        asm volatile("cp.async.commit_group;" ::: "memory");
    };
    auto computec = [&](int buf) {
        const uint32_t* Ab = Asm + buf * 128 * (SSTRH / 2);
        const uint32_t* Bb = Bsm + buf * 64 * (SSTRH / 2);
#pragma unroll
        for (int ks = 0; ks < 4; ks++) {
            const int kw = ks * 8;
            uint32_t af[2][4], bf[4][2];
#pragma unroll
            for (int mf = 0; mf < 2; mf++) {
                int r = wm + mf * 16 + gid;
                const uint32_t* p0 = Ab + r * (SSTRH / 2) + kw + tig;
                const uint32_t* p1 = Ab + (r + 8) * (SSTRH / 2) + kw + tig;
                af[mf][0] = p0[0];
                af[mf][1] = p1[0];
                af[mf][2] = p0[4];
                af[mf][3] = p1[4];
            }
#pragma unroll
            for (int nf = 0; nf < 4; nf++) {
                int r = wn + nf * 8 + gid;
                const uint32_t* p = Bb + r * (SSTRH / 2) + kw + tig;
                bf[nf][0] = p[0];
                bf[nf][1] = p[4];
            }
#pragma unroll
            for (int mf = 0; mf < 2; mf++)
#pragma unroll
                for (int nf = 0; nf < 4; nf++) mma_bf16(acc[mf][nf], af[mf], bf[nf]);
        }
    };

    loadc(0, 0);
    for (int c = 0; c < nch; c++) {
        if (c + 1 < nch) {
            loadc(c + 1, (c + 1) & 1);
            asm volatile("cp.async.wait_group 1;" ::: "memory");
        } else {
            asm volatile("cp.async.wait_group 0;" ::: "memory");
        }
        __syncthreads();
        computec(c & 1);
        __syncthreads();
    }

#pragma unroll
    for (int mf = 0; mf < 2; mf++) {
#pragma unroll
        for (int nf = 0; nf < 4; nf++) {
            int col = n0 + wn + nf * 8 + tig * 2;
            int r0 = m0 + wm + mf * 16 + gid;
            *(float2*)(dst + (size_t)r0 * N + col) =
                make_float2(acc[mf][nf][0], acc[mf][nf][1]);
            if (diagflag) {
                if (r0 == col)     g_invn[r0] = rsqrtf(fmaxf(acc[mf][nf][0], 1e-30f));
                if (r0 == col + 1) g_invn[r0] = rsqrtf(fmaxf(acc[mf][nf][1], 1e-30f));
            }
            int r1 = r0 + 8;
            *(float2*)(dst + (size_t)r1 * N + col) =
                make_float2(acc[mf][nf][2], acc[mf][nf][3]);
            if (diagflag) {
                if (r1 == col)     g_invn[r1] = rsqrtf(fmaxf(acc[mf][nf][2], 1e-30f));
                if (r1 == col + 1) g_invn[r1] = rsqrtf(fmaxf(acc[mf][nf][3], 1e-30f));
            }
        }
    }
}

// ------ GEMM variant B: 64x32 tile, bf16 out, deep pipeline ------------------
__device__ __noinline__ void gemm_small(const __nv_bfloat16* A, const __nv_bfloat16* B,
                                        __nv_bfloat16* dst, int N, int K, int nch,
                                        int m0, int n0, __nv_bfloat16* smh) {
    const int tid = threadIdx.x, wid = tid >> 5, lane = tid & 31;
    const int gid = lane >> 2, tig = lane & 3;
    const int wm = (wid & 3) * 16, wn = (wid >> 2) * 16;
    const uint32_t sbase = (uint32_t)__cvta_generic_to_shared(smh);
    const uint32_t* Asm = (const uint32_t*)smh;
    const uint32_t* Bsm = (const uint32_t*)(smh + 2 * 64 * SSTRH);

    float acc[2][4];
#pragma unroll
    for (int a = 0; a < 2; a++)
#pragma unroll
        for (int c = 0; c < 4; c++) acc[a][c] = 0.f;

    auto loadc = [&](int kc, int buf) {
        const __nv_bfloat16* Ab = A + (size_t)m0 * K + kc * KCHH;
        const __nv_bfloat16* Bb = B + (size_t)n0 * K + kc * KCHH;
        uint32_t as0 = sbase + (uint32_t)(buf * 64 * SSTRH) * 2u;
        uint32_t bs0 = sbase + (uint32_t)((2 * 64 + buf * 32) * SSTRH) * 2u;
#pragma unroll
        for (int i = 0; i < 2; i++) {
            int idx = tid + i * 256;
            int row = idx >> 3, kq = (idx & 7) * 8;
            cp16(as0 + (uint32_t)(row * SSTRH + kq) * 2u, Ab + (size_t)row * K + kq);
        }
        {
            int row = tid >> 3, kq = (tid & 7) * 8;
            cp16(bs0 + (uint32_t)(row * SSTRH + kq) * 2u, Bb + (size_t)row * K + kq);
        }
        asm volatile("cp.async.commit_group;" ::: "memory");
    };
    auto computec = [&](int buf) {
        const uint32_t* Ab = Asm + buf * 64 * (SSTRH / 2);
        const uint32_t* Bb = Bsm + buf * 32 * (SSTRH / 2);
#pragma unroll
        for (int ks = 0; ks < 4; ks++) {
            const int kw = ks * 8;
            uint32_t af[4], bf[2][2];
            {
                int r = wm + gid;
                const uint32_t* p0 = Ab + r * (SSTRH / 2) + kw + tig;
                const uint32_t* p1 = Ab + (r + 8) * (SSTRH / 2) + kw + tig;
                af[0] = p0[0];
                af[1] = p1[0];
                af[2] = p0[4];
                af[3] = p1[4];
            }
#pragma unroll
            for (int nf = 0; nf < 2; nf++) {
                int r = wn + nf * 8 + gid;
                const uint32_t* p = Bb + r * (SSTRH / 2) + kw + tig;
                bf[nf][0] = p[0];
                bf[nf][1] = p[4];
            }
#pragma unroll
            for (int nf = 0; nf < 2; nf++) mma_bf16(acc[nf], af, bf[nf]);
        }
    };

    loadc(0, 0);
    for (int c = 0; c < nch; c++) {
        if (c + 1 < nch) {
            loadc(c + 1, (c + 1) & 1);
            asm volatile("cp.async.wait_group 1;" ::: "memory");
        } else {
            asm volatile("cp.async.wait_group 0;" ::: "memory");
        }
        __syncthreads();
        computec(c & 1);
        __syncthreads();
    }

#pragma unroll
    for (int nf = 0; nf < 2; nf++) {
        int col = n0 + wn + nf * 8 + tig * 2;
        int r0 = m0 + wm + gid;
        int r1 = r0 + 8;
        *(uint32_t*)(dst + (size_t)r0 * N + col) = bf2pack(acc[nf][0], acc[nf][1]);
        *(uint32_t*)(dst + (size_t)r1 * N + col) = bf2pack(acc[nf][2], acc[nf][3]);
    }
}

// ---------------- softmax+spmm phase (enc, bf16 out) -------------------------
__device__ void softmax_phase(const float* __restrict__ B, char* smx) {
    __shared__ float sh[32];
    __shared__ int cnt;
    int* scols = (int*)smx;
    float* svals = (float*)(smx + 4096);
    int t = threadIdx.x;
    for (int i = 0; i < 8; i++) {
        int r = blockIdx.x * 8 + i;
        const float* gr = g_G + (size_t)r * CP;
        float ir = g_invn[r];
        float v[4];
        float mx = -1e30f;
#pragma unroll
        for (int j = 0; j < 4; j++) {
            int c = t + j * 256;
            float x = (c < C_CLS && r < C_CLS) ? gr[c] * ir * g_invn[c] : -1e30f;
            v[j] = x;
            if (x > 0.5f) mx = fmaxf(mx, x);
        }
        mx = blockMax(mx, sh);
        float m10 = mx * 10.f;
        float e[4];
        float s = 0.f;
#pragma unroll
        for (int j = 0; j < 4; j++) {
            e[j] = (v[j] > 0.5f) ? expf(v[j] * 10.f - m10) : 0.f;
            s += e[j];
        }
        s = blockSum(s, sh);
        float inv = 1.f / s;
        if (t == 0) cnt = 0;
        __syncthreads();
#pragma unroll
        for (int j = 0; j < 4; j++) {
            if (e[j] > 0.f) {
                int slot = atomicAdd(&cnt, 1);
                scols[slot] = t + j * 256;
                svals[slot] = e[j] * inv;
            }
        }
        __syncthreads();
        int n = cnt;
        float2 acc = make_float2(0.f, 0.f);
        for (int k = 0; k < n; k++) {
            int c = scols[k];
            float w = svals[k];
            float2 b = ((const float2*)(B + (size_t)c * AD))[t];
            acc.x += w * b.x;
            acc.y += w * b.y;
        }
        ((uint32_t*)g_enc_bf)[(size_t)r * (AD / 2) + t] = bf2pack(acc.x, acc.y);
        __syncthreads();
    }
}

// ---------------- megakernel (P0..P6) ----------------------------------------
__global__ __launch_bounds__(256, 1) void mega_k(const float* __restrict__ attrs,
                                                 const float* __restrict__ att_h,
                                                 const float* __restrict__ att_g,
                                                 const int* __restrict__ tpl,
                                                 float* __restrict__ out) {
    extern __shared__ char smx[];
    __nv_bfloat16* smh = (__nv_bfloat16*)smx;
    const int tid = threadIdx.x, bid = blockIdx.x;

    // P0a: cvt attrs fp32 -> bf16 (zero-padded rows)
    {
        const float4* src = (const float4*)attrs;
        uint2* dst = (uint2*)g_attr_bf;
#pragma unroll
        for (int i = 0; i < 4; i++) {
            int idx = bid * 1024 + i * 256 + tid;
            int row = idx >> 7;
            float4 v = make_float4(0.f, 0.f, 0.f, 0.f);
            if (row < C_CLS) v = src[(size_t)row * 128 + (idx & 127)];
            uint2 o;
            o.x = bf2pack(v.x, v.y);
            o.y = bf2pack(v.z, v.w);
            dst[idx] = o;
        }
    }
    // P0b: transpose att_h / att_g -> bf16 [HD,AD]
    {
        float* tb = (float*)smx;
        int ty = tid >> 5, tx = tid & 31;
        for (int ii = 0; ii < 2; ii++) {
            int j = bid * 2 + ii;
            const float* in = (j < 128) ? att_h : att_g;
            __nv_bfloat16* o = (j < 128) ? g_hT_bf : g_gT_bf;
            int jj = j & 127;
            int h0 = (jj & 7) * 32, a0 = (jj >> 3) * 32;
            __syncthreads();
#pragma unroll
            for (int s = 0; s < 4; s++)
                tb[(ty + s * 8) * 33 + tx] = in[(size_t)(a0 + ty + s * 8) * HD + h0 + tx];
            __syncthreads();
#pragma unroll
            for (int s = 0; s < 4; s++)
                o[(size_t)(h0 + ty + s * 8) * AD + a0 + tx] =
                    __float2bfloat16(tb[tx * 33 + ty + s * 8]);
        }
    }
    gridbar();
    // P1: p = attr @ att_h  (64x32 tiles, nch=8) -> bf16
    {
        int bx = bid & 7, by = bid >> 3;
        gemm_small(g_attr_bf, g_hT_bf, g_p_bf, HD, AD, 8, by * 64, bx * 32, smh);
    }
    gridbar();
    // P2: G1 = p @ p^T, fused diag rsqrt
    {
        int bx = bid & 15, by = bid >> 4;
        gemm_phase(g_p_bf, g_p_bf, g_G, CP, HD, 4, by * 128, bx * 64, 1, smh);
    }
    gridbar();
    // P3: enc = softmax(G1) @ attrs (bf16)
    softmax_phase(attrs, smx);
    gridbar();
    // P4: q = enc @ att_g (64x32 tiles, nch=8) -> bf16
    {
        int bx = bid & 7, by = bid >> 3;
        gemm_small(g_enc_bf, g_gT_bf, g_q_bf, HD, AD, 8, by * 64, bx * 32, smh);
    }
    gridbar();
    // P5: G2 = q @ q^T, fused diag rsqrt
    {
        int bx = bid & 15, by = bid >> 4;
        gemm_phase(g_q_bf, g_q_bf, g_G, CP, HD, 4, by * 128, bx * 64, 1, smh);
    }
    gridbar();
    // P6: wait for proto partial sums, then out = softmax(G2) @ protos
    {
        if (tid == 0) {
            while (*(volatile int*)&g_pdone < 4 * C_CLS) __nanosleep(128);
        }
        __syncthreads();
        __threadfence();
        __shared__ float sh[32];
        __shared__ int cnt;
        int* scols = (int*)smx;
        float* svals = (float*)(smx + 4096);
        int t = tid;
        for (int i = 0; i < 8; i++) {
            int r = bid * 8 + i;
            if (r >= C_CLS) break;
            const float* gr = g_G + (size_t)r * CP;
            float ir = g_invn[r];
            float v[4];
            float mx = -1e30f;
#pragma unroll
            for (int j = 0; j < 4; j++) {
                int c = t + j * 256;
                float x = (c < C_CLS) ? gr[c] * ir * g_invn[c] : -1e30f;
                v[j] = x;
                if (x > 0.5f) mx = fmaxf(mx, x);
            }
            mx = blockMax(mx, sh);
            float m10 = mx * 10.f;
            float e[4];
            float s = 0.f;
#pragma unroll
            for (int j = 0; j < 4; j++) {
                e[j] = (v[j] > 0.5f) ? expf(v[j] * 10.f - m10) : 0.f;
                s += e[j];
            }
            s = blockSum(s, sh);
            float inv = 1.f / s;
            if (t == 0) cnt = 0;
            __syncthreads();
#pragma unroll
            for (int j = 0; j < 4; j++) {
                if (e[j] > 0.f) {
                    int slot = atomicAdd(&cnt, 1);
                    scols[slot] = t + j * 256;
                    svals[slot] = e[j] * inv;
                }
            }
            __syncthreads();
            int n = cnt;
            float2 acc = make_float2(0.f, 0.f);
            for (int k = 0; k < n; k++) {
                int c = scols[k];
                int pc = tpl[c];
                int cc = g_counts[pc];
                float w = svals[k] * (cc > 0 ? 1.f / (float)cc : 0.f);
                float2 b0 = ((const float2*)(g_meanp + (size_t)(4 * pc + 0) * AD))[t];
                float2 b1 = ((const float2*)(g_meanp + (size_t)(4 * pc + 1) * AD))[t];
                float2 b2 = ((const float2*)(g_meanp + (size_t)(4 * pc + 2) * AD))[t];
                float2 b3 = ((const float2*)(g_meanp + (size_t)(4 * pc + 3) * AD))[t];
                acc.x += w * (b0.x + b1.x + b2.x + b3.x);
                acc.y += w * (b0.y + b1.y + b2.y + b3.y);
            }
            ((float2*)out)[(size_t)r * (AD / 2) + t] = acc;
            __syncthreads();
        }
    }
    gridbar();
    if (bid == 0 && tid == 0) g_pdone = 0;   // reset for next graph replay
}

// ---------------- launch ------------------------------------------------------
extern "C" void kernel_launch(void* const* d_in, const int* in_sizes, int n_in,
                              void* d_out, int out_size) {
    const float* img    = (const float*)d_in[0];
    const float* attrs  = (const float*)d_in[1];
    const float* att_g  = (const float*)d_in[2];
    const float* att_h  = (const float*)d_in[3];
    const int*   labels = (const int*)d_in[4];
    const int*   tpl    = (const int*)d_in[5];
    float* out = (float*)d_out;
    int N = in_sizes[4];
    (void)n_in; (void)out_size;

    cudaFuncSetAttribute(mega_k, cudaFuncAttributeMaxDynamicSharedMemorySize, GSMEM);

    void *p_counts, *p_cursor;
    cudaGetSymbolAddress(&p_counts, g_counts);
    cudaGetSymbolAddress(&p_cursor, g_cursor);

    int prLo, prHi;
    cudaDeviceGetStreamPriorityRange(&prLo, &prHi);
    cudaStream_t s1;
    cudaStreamCreateWithPriority(&s1, cudaStreamNonBlocking, prHi);
    cudaEvent_t evF, evJ;
    cudaEventCreateWithFlags(&evF, cudaEventDisableTiming);
    cudaEventCreateWithFlags(&evJ, cudaEventDisableTiming);

    cudaEventRecord(evF, 0);
    cudaStreamWaitEvent(s1, evF, 0);

    // --- high-priority side stream: sort + class partial sums ---
    cudaMemsetAsync(p_counts, 0, C_CLS * sizeof(int), s1);
    cudaMemsetAsync(p_cursor, 0, C_CLS * sizeof(int), s1);
    hist_scan_k<<<HIST_BLOCKS, 256, 0, s1>>>(labels, N);
    scatter_k<<<(N + 1023) / 1024, 256, 0, s1>>>(labels, N);
    class_mean4_k<<<4 * C_CLS, 256, 0, s1>>>(img);
    cudaEventRecord(evJ, s1);

    // --- main stream: megakernel P0..P6 (device-side join with protos) ---
    mega_k<<<GRID_MAIN, 256, GSMEM>>>(attrs, att_h, att_g, tpl, out);

    // join side stream into origin stream for capture correctness
    cudaStreamWaitEvent(0, evJ, 0);
}

// round 15
// speedup vs baseline: 1.2038x; 1.2038x over previous
#include <cuda_runtime.h>
#include <cuda_bf16.h>
#include <cstdint>
#include <math.h>

#define C_CLS 1000
#define CP    1024
#define AD    512
#define HD    256
#define NMAX  131072
#define KCHH  64
#define SSTRH 72
#define GRID_MAIN 128
#define GSMEM ((2*128*SSTRH + 2*64*SSTRH) * 2)   // 55296 bytes

// ---------------- scratch ----------------------------------------------------
__device__ __nv_bfloat16 g_attr_bf[CP * AD];
__device__ __nv_bfloat16 g_p_bf[CP * HD];
__device__ __nv_bfloat16 g_q_bf[CP * HD];
__device__ __nv_bfloat16 g_enc_bf[CP * AD];
__device__ __nv_bfloat16 g_hT_bf[HD * AD];
__device__ __nv_bfloat16 g_gT_bf[HD * AD];
__device__ float g_G[CP * CP];
__device__ float g_meanp[4 * C_CLS * AD];
__device__ float g_invn[CP];
__device__ int   g_counts[C_CLS];
__device__ int   g_offsets[C_CLS];
__device__ int   g_cursor[C_CLS];
__device__ int   g_sorted[NMAX];
__device__ int   g_done = 0;
__device__ int   g_barc = 0;
__device__ volatile int g_barg = 0;

// ---------------- helpers ----------------------------------------------------
__device__ __forceinline__ float warpSum(float v) {
#pragma unroll
    for (int o = 16; o; o >>= 1) v += __shfl_xor_sync(0xffffffffu, v, o);
    return v;
}
__device__ __forceinline__ float warpMax(float v) {
#pragma unroll
    for (int o = 16; o; o >>= 1) v = fmaxf(v, __shfl_xor_sync(0xffffffffu, v, o));
    return v;
}
__device__ __forceinline__ float blockSum(float v, float* sh) {
    int t = threadIdx.x, lane = t & 31, w = t >> 5, nw = blockDim.x >> 5;
    v = warpSum(v);
    if (!lane) sh[w] = v;
    __syncthreads();
    if (w == 0) {
        float x = (lane < nw) ? sh[lane] : 0.f;
        x = warpSum(x);
        if (!lane) sh[0] = x;
    }
    __syncthreads();
    float r = sh[0];
    __syncthreads();
    return r;
}
__device__ __forceinline__ float blockMax(float v, float* sh) {
    int t = threadIdx.x, lane = t & 31, w = t >> 5, nw = blockDim.x >> 5;
    v = warpMax(v);
    if (!lane) sh[w] = v;
    __syncthreads();
    if (w == 0) {
        float x = (lane < nw) ? sh[lane] : -1e30f;
        x = warpMax(x);
        if (!lane) sh[0] = x;
    }
    __syncthreads();
    float r = sh[0];
    __syncthreads();
    return r;
}
__device__ __forceinline__ void cp16(uint32_t dst, const void* src) {
    asm volatile("cp.async.ca.shared.global [%0], [%1], 16;" :: "r"(dst), "l"(src));
}
__device__ __forceinline__ uint32_t bf2pack(float a, float b) {
    __nv_bfloat162 h = __floats2bfloat162_rn(a, b);
    return *(uint32_t*)&h;
}
__device__ __forceinline__ void mma_bf16(float* c, const uint32_t* a, const uint32_t* b) {
    asm volatile(
        "mma.sync.aligned.m16n8k16.row.col.f32.bf16.bf16.f32 "
        "{%0,%1,%2,%3}, {%4,%5,%6,%7}, {%8,%9}, {%0,%1,%2,%3};"
        : "+f"(c[0]), "+f"(c[1]), "+f"(c[2]), "+f"(c[3])
        : "r"(a[0]), "r"(a[1]), "r"(a[2]), "r"(a[3]), "r"(b[0]), "r"(b[1]));
}
__device__ __forceinline__ void gridbar() {
    __syncthreads();
    if (threadIdx.x == 0) {
        __threadfence();
        int gen = g_barg;
        if (atomicAdd(&g_barc, 1) == GRID_MAIN - 1) {
            g_barc = 0;
            __threadfence();
            g_barg = gen + 1;
        } else {
            while (g_barg == gen) { }
        }
    }
    __syncthreads();
}

// ------- fused hist + scan (last-block pattern) ------------------------------
#define HIST_BLOCKS 25
__global__ __launch_bounds__(256) void hist_scan_k(const int* __restrict__ labels, int n) {
    __shared__ int h[C_CLS];
    __shared__ int amLast;
    const int tid = threadIdx.x;
    for (int i = tid; i < C_CLS; i += 256) h[i] = 0;
    __syncthreads();
    for (int i = blockIdx.x * blockDim.x + tid; i < n; i += gridDim.x * blockDim.x)
        atomicAdd(&h[labels[i]], 1);
    __syncthreads();
    for (int i = tid; i < C_CLS; i += 256)
        if (h[i]) atomicAdd(&g_counts[i], h[i]);
    __threadfence();
    if (tid == 0) amLast = (atomicAdd(&g_done, 1) == HIST_BLOCKS - 1);
    __syncthreads();
    if (amLast && tid < 32) {
        int lane = tid;
        int base = lane * 32;
        int loc[32];
        int s = 0;
#pragma unroll
        for (int j = 0; j < 32; j++) {
            int idx = base + j;
            int c = (idx < C_CLS) ? g_counts[idx] : 0;
            loc[j] = s;
            s += c;
        }
        int inc = s;
#pragma unroll
        for (int o = 1; o < 32; o <<= 1) {
            int nv = __shfl_up_sync(0xffffffffu, inc, o);
            if (lane >= o) inc += nv;
        }
        int excl = inc - s;
#pragma unroll
        for (int j = 0; j < 32; j++) {
            int idx = base + j;
            if (idx < C_CLS) g_offsets[idx] = excl + loc[j];
        }
        if (lane == 0) g_done = 0;
    }
}
__global__ __launch_bounds__(256) void scatter_k(const int* __restrict__ labels, int n) {
    int i0 = (blockIdx.x * blockDim.x + threadIdx.x) * 4;
    int l[4], pos[4];
#pragma unroll
    for (int j = 0; j < 4; j++) {
        int i = i0 + j;
        if (i < n) {
            l[j] = labels[i];
            pos[j] = atomicAdd(&g_cursor[l[j]], 1);
        } else l[j] = -1;
    }
#pragma unroll
    for (int j = 0; j < 4; j++)
        if (l[j] >= 0) g_sorted[g_offsets[l[j]] + pos[j]] = i0 + j;
}
// ---- class partial sums: 4 CTAs/class, 256 threads (2 row-groups x 128 cols)
__global__ __launch_bounds__(256) void class_mean4_k(const float* __restrict__ img) {
    int c = blockIdx.x >> 2, q = blockIdx.x & 3;
    int t = threadIdx.x;
    int col = t & 127, rg = t >> 7;
    int cnt = g_counts[c], off = g_offsets[c];
    int lo = (cnt * q) >> 2, hi = (cnt * (q + 1)) >> 2;
    int len = hi - lo;
    __shared__ int idx[128];
    __shared__ float4 red[128];
    int lim = len < 128 ? len : 128;
    for (int j = t; j < lim; j += 256) idx[j] = g_sorted[off + lo + j];
    __syncthreads();
    float4 acc = make_float4(0.f, 0.f, 0.f, 0.f);
    int j = rg;
    for (; j + 6 < lim; j += 8) {
        float4 a = ((const float4*)(img + (size_t)idx[j] * AD))[col];
        float4 b = ((const float4*)(img + (size_t)idx[j + 2] * AD))[col];
        float4 d = ((const float4*)(img + (size_t)idx[j + 4] * AD))[col];
        float4 e = ((const float4*)(img + (size_t)idx[j + 6] * AD))[col];
        acc.x += a.x + b.x + d.x + e.x;
        acc.y += a.y + b.y + d.y + e.y;
        acc.z += a.z + b.z + d.z + e.z;
        acc.w += a.w + b.w + d.w + e.w;
    }
    for (; j < lim; j += 2) {
        float4 a = ((const float4*)(img + (size_t)idx[j] * AD))[col];
        acc.x += a.x; acc.y += a.y; acc.z += a.z; acc.w += a.w;
    }
    for (j = lim + rg; j < len; j += 2) {
        float4 a = ((const float4*)(img + (size_t)g_sorted[off + lo + j] * AD))[col];
        acc.x += a.x; acc.y += a.y; acc.z += a.z; acc.w += a.w;
    }
    if (rg == 1) red[col] = acc;
    __syncthreads();
    if (rg == 0) {
        float4 o2 = red[col];
        acc.x += o2.x; acc.y += o2.y; acc.z += o2.z; acc.w += o2.w;
        ((float4*)(g_meanp + (size_t)blockIdx.x * AD))[col] = acc;
    }
}

// ------ GEMM variant A: 128x64 tile, fp32 out (+optional diag) ---------------
__device__ __noinline__ void gemm_phase(const __nv_bfloat16* A, const __nv_bfloat16* B,
                                        float* dst, int N, int K, int nch,
                                        int m0, int n0, int diagflag,
                                        __nv_bfloat16* smh) {
    const int tid = threadIdx.x, wid = tid >> 5, lane = tid & 31;
    const int gid = lane >> 2, tig = lane & 3;
    const int wm = (wid & 3) * 32, wn = (wid >> 2) * 32;
    const uint32_t sbase = (uint32_t)__cvta_generic_to_shared(smh);
    const uint32_t* Asm = (const uint32_t*)smh;
    const uint32_t* Bsm = (const uint32_t*)(smh + 2 * 128 * SSTRH);

    float acc[2][4][4];
#pragma unroll
    for (int a = 0; a < 2; a++)
#pragma unroll
        for (int b = 0; b < 4; b++)
#pragma unroll
            for (int c = 0; c < 4; c++) acc[a][b][c] = 0.f;

    auto loadc = [&](int kc, int buf) {
        const __nv_bfloat16* Ab = A + (size_t)m0 * K + kc * KCHH;
        const __nv_bfloat16* Bb = B + (size_t)n0 * K + kc * KCHH;
        uint32_t as0 = sbase + (uint32_t)(buf * 128 * SSTRH) * 2u;
        uint32_t bs0 = sbase + (uint32_t)(2 * 128 * SSTRH + buf * 64 * SSTRH) * 2u;
#pragma unroll
        for (int i = 0; i < 4; i++) {
            int idx = tid + i * 256;
            int row = idx >> 3, kq = (idx & 7) * 8;
            cp16(as0 + (uint32_t)(row * SSTRH + kq) * 2u, Ab + (size_t)row * K + kq);
        }
#pragma unroll
        for (int i = 0; i < 2; i++) {
            int idx = tid + i * 256;
            int row = idx >> 3, kq = (idx & 7) * 8;
            cp16(bs0 + (uint32_t)(row * SSTRH + kq) * 2u, Bb + (size_t)row * K + kq);
        }
        asm volatile("cp.async.commit_group;" ::: "memory");
    };
    auto computec = [&](int buf) {
        const uint32_t* Ab = Asm + buf * 128 * (SSTRH / 2);
        const uint32_t* Bb = Bsm + buf * 64 * (SSTRH / 2);
#pragma unroll
        for (int ks = 0; ks < 4; ks++) {
            const int kw = ks * 8;
            uint32_t af[2][4], bf[4][2];
#pragma unroll
            for (int mf = 0; mf < 2; mf++) {
                int r = wm + mf * 16 + gid;
                const uint32_t* p0 = Ab + r * (SSTRH / 2) + kw + tig;
                const uint32_t* p1 = Ab + (r + 8) * (SSTRH / 2) + kw + tig;
                af[mf][0] = p0[0];
                af[mf][1] = p1[0];
                af[mf][2] = p0[4];
                af[mf][3] = p1[4];
            }
#pragma unroll
            for (int nf = 0; nf < 4; nf++) {
                int r = wn + nf * 8 + gid;
                const uint32_t* p = Bb + r * (SSTRH / 2) + kw + tig;
                bf[nf][0] = p[0];
                bf[nf][1] = p[4];
            }
#pragma unroll
            for (int mf = 0; mf < 2; mf++)
#pragma unroll
                for (int nf = 0; nf < 4; nf++) mma_bf16(acc[mf][nf], af[mf], bf[nf]);
        }
    };

    loadc(0, 0);
    for (int c = 0; c < nch; c++) {
        if (c + 1 < nch) {
            loadc(c + 1, (c + 1) & 1);
            asm volatile("cp.async.wait_group 1;" ::: "memory");
        } else {
            asm volatile("cp.async.wait_group 0;" ::: "memory");
        }
        __syncthreads();
        computec(c & 1);
        __syncthreads();
    }

#pragma unroll
    for (int mf = 0; mf < 2; mf++) {
#pragma unroll
        for (int nf = 0; nf < 4; nf++) {
            int col = n0 + wn + nf * 8 + tig * 2;
            int r0 = m0 + wm + mf * 16 + gid;
            *(float2*)(dst + (size_t)r0 * N + col) =
                make_float2(acc[mf][nf][0], acc[mf][nf][1]);
            if (diagflag) {
                if (r0 == col)     g_invn[r0] = rsqrtf(fmaxf(acc[mf][nf][0], 1e-30f));
                if (r0 == col + 1) g_invn[r0] = rsqrtf(fmaxf(acc[mf][nf][1], 1e-30f));
            }
            int r1 = r0 + 8;
            *(float2*)(dst + (size_t)r1 * N + col) =
                make_float2(acc[mf][nf][2], acc[mf][nf][3]);
            if (diagflag) {
                if (r1 == col)     g_invn[r1] = rsqrtf(fmaxf(acc[mf][nf][2], 1e-30f));
                if (r1 == col + 1) g_invn[r1] = rsqrtf(fmaxf(acc[mf][nf][3], 1e-30f));
            }
        }
    }
}

// ------ GEMM variant B: 64x32 tile, bf16 out, deep pipeline ------------------
__device__ __noinline__ void gemm_small(const __nv_bfloat16* A, const __nv_bfloat16* B,
                                        __nv_bfloat16* dst, int N, int K, int nch,
                                        int m0, int n0, __nv_bfloat16* smh) {
    const int tid = threadIdx.x, wid = tid >> 5, lane = tid & 31;
    const int gid = lane >> 2, tig = lane & 3;
    const int wm = (wid & 3) * 16, wn = (wid >> 2) * 16;
    const uint32_t sbase = (uint32_t)__cvta_generic_to_shared(smh);
    const uint32_t* Asm = (const uint32_t*)smh;
    const uint32_t* Bsm = (const uint32_t*)(smh + 2 * 64 * SSTRH);

    float acc[2][4];
#pragma unroll
    for (int a = 0; a < 2; a++)
#pragma unroll
        for (int c = 0; c < 4; c++) acc[a][c] = 0.f;

    auto loadc = [&](int kc, int buf) {
        const __nv_bfloat16* Ab = A + (size_t)m0 * K + kc * KCHH;
        const __nv_bfloat16* Bb = B + (size_t)n0 * K + kc * KCHH;
        uint32_t as0 = sbase + (uint32_t)(buf * 64 * SSTRH) * 2u;
        uint32_t bs0 = sbase + (uint32_t)((2 * 64 + buf * 32) * SSTRH) * 2u;
#pragma unroll
        for (int i = 0; i < 2; i++) {
            int idx = tid + i * 256;
            int row = idx >> 3, kq = (idx & 7) * 8;
            cp16(as0 + (uint32_t)(row * SSTRH + kq) * 2u, Ab + (size_t)row * K + kq);
        }
        {
            int row = tid >> 3, kq = (tid & 7) * 8;
            cp16(bs0 + (uint32_t)(row * SSTRH + kq) * 2u, Bb + (size_t)row * K + kq);
        }
        asm volatile("cp.async.commit_group;" ::: "memory");
    };
    auto computec = [&](int buf) {
        const uint32_t* Ab = Asm + buf * 64 * (SSTRH / 2);
        const uint32_t* Bb = Bsm + buf * 32 * (SSTRH / 2);
#pragma unroll
        for (int ks = 0; ks < 4; ks++) {
            const int kw = ks * 8;
            uint32_t af[4], bf[2][2];
            {
                int r = wm + gid;
                const uint32_t* p0 = Ab + r * (SSTRH / 2) + kw + tig;
                const uint32_t* p1 = Ab + (r + 8) * (SSTRH / 2) + kw + tig;
                af[0] = p0[0];
                af[1] = p1[0];
                af[2] = p0[4];
                af[3] = p1[4];
            }
#pragma unroll
            for (int nf = 0; nf < 2; nf++) {
                int r = wn + nf * 8 + gid;
                const uint32_t* p = Bb + r * (SSTRH / 2) + kw + tig;
                bf[nf][0] = p[0];
                bf[nf][1] = p[4];
            }
#pragma unroll
            for (int nf = 0; nf < 2; nf++) mma_bf16(acc[nf], af, bf[nf]);
        }
    };

    loadc(0, 0);
    for (int c = 0; c < nch; c++) {
        if (c + 1 < nch) {
            loadc(c + 1, (c + 1) & 1);
            asm volatile("cp.async.wait_group 1;" ::: "memory");
        } else {
            asm volatile("cp.async.wait_group 0;" ::: "memory");
        }
        __syncthreads();
        computec(c & 1);
        __syncthreads();
    }

#pragma unroll
    for (int nf = 0; nf < 2; nf++) {
        int col = n0 + wn + nf * 8 + tig * 2;
        int r0 = m0 + wm + gid;
        int r1 = r0 + 8;
        *(uint32_t*)(dst + (size_t)r0 * N + col) = bf2pack(acc[nf][0], acc[nf][1]);
        *(uint32_t*)(dst + (size_t)r1 * N + col) = bf2pack(acc[nf][2], acc[nf][3]);
    }
}

// ---------------- softmax+spmm phase (enc, bf16 out) -------------------------
__device__ void softmax_phase(const float* __restrict__ B, char* smx) {
    __shared__ float sh[32];
    __shared__ int cnt;
    int* scols = (int*)smx;
    float* svals = (float*)(smx + 4096);
    int t = threadIdx.x;
    for (int i = 0; i < 8; i++) {
        int r = blockIdx.x * 8 + i;
        const float* gr = g_G + (size_t)r * CP;
        float ir = g_invn[r];
        float v[4];
        float mx = -1e30f;
#pragma unroll
        for (int j = 0; j < 4; j++) {
            int c = t + j * 256;
            float x = (c < C_CLS && r < C_CLS) ? gr[c] * ir * g_invn[c] : -1e30f;
            v[j] = x;
            if (x > 0.5f) mx = fmaxf(mx, x);
        }
        mx = blockMax(mx, sh);
        float m10 = mx * 10.f;
        float e[4];
        float s = 0.f;
#pragma unroll
        for (int j = 0; j < 4; j++) {
            e[j] = (v[j] > 0.5f) ? expf(v[j] * 10.f - m10) : 0.f;
            s += e[j];
        }
        s = blockSum(s, sh);
        float inv = 1.f / s;
        if (t == 0) cnt = 0;
        __syncthreads();
#pragma unroll
        for (int j = 0; j < 4; j++) {
            if (e[j] > 0.f) {
                int slot = atomicAdd(&cnt, 1);
                scols[slot] = t + j * 256;
                svals[slot] = e[j] * inv;
            }
        }
        __syncthreads();
        int n = cnt;
        float2 acc = make_float2(0.f, 0.f);
        for (int k = 0; k < n; k++) {
            int c = scols[k];
            float w = svals[k];
            float2 b = ((const float2*)(B + (size_t)c * AD))[t];
            acc.x += w * b.x;
            acc.y += w * b.y;
        }
        ((uint32_t*)g_enc_bf)[(size_t)r * (AD / 2) + t] = bf2pack(acc.x, acc.y);
        __syncthreads();
    }
}

// ---------------- megakernel (P0..P5) ----------------------------------------
__global__ __launch_bounds__(256, 1) void mega_k(const float* __restrict__ attrs,
                                                 const float* __restrict__ att_h,
                                                 const float* __restrict__ att_g) {
    extern __shared__ char smx[];
    __nv_bfloat16* smh = (__nv_bfloat16*)smx;
    const int tid = threadIdx.x, bid = blockIdx.x;

    // P0a: cvt attrs fp32 -> bf16 (zero-padded rows)
    {
        const float4* src = (const float4*)attrs;
        uint2* dst = (uint2*)g_attr_bf;
#pragma unroll
        for (int i = 0; i < 4; i++) {
            int idx = bid * 1024 + i * 256 + tid;
            int row = idx >> 7;
            float4 v = make_float4(0.f, 0.f, 0.f, 0.f);
            if (row < C_CLS) v = src[(size_t)row * 128 + (idx & 127)];
            uint2 o;
            o.x = bf2pack(v.x, v.y);
            o.y = bf2pack(v.z, v.w);
            dst[idx] = o;
        }
    }
    // P0b: transpose att_h / att_g -> bf16 [HD,AD]
    {
        float* tb = (float*)smx;
        int ty = tid >> 5, tx = tid & 31;
        for (int ii = 0; ii < 2; ii++) {
            int j = bid * 2 + ii;
            const float* in = (j < 128) ? att_h : att_g;
            __nv_bfloat16* o = (j < 128) ? g_hT_bf : g_gT_bf;
            int jj = j & 127;
            int h0 = (jj & 7) * 32, a0 = (jj >> 3) * 32;
            __syncthreads();
#pragma unroll
            for (int s = 0; s < 4; s++)
                tb[(ty + s * 8) * 33 + tx] = in[(size_t)(a0 + ty + s * 8) * HD + h0 + tx];
            __syncthreads();
#pragma unroll
            for (int s = 0; s < 4; s++)
                o[(size_t)(h0 + ty + s * 8) * AD + a0 + tx] =
                    __float2bfloat16(tb[tx * 33 + ty + s * 8]);
        }
    }
    gridbar();
    // P1: p = attr @ att_h  (64x32 tiles, nch=8) -> bf16
    {
        int bx = bid & 7, by = bid >> 3;
        gemm_small(g_attr_bf, g_hT_bf, g_p_bf, HD, AD, 8, by * 64, bx * 32, smh);
    }
    gridbar();
    // P2: G1 = p @ p^T, fused diag rsqrt
    {
        int bx = bid & 15, by = bid >> 4;
        gemm_phase(g_p_bf, g_p_bf, g_G, CP, HD, 4, by * 128, bx * 64, 1, smh);
    }
    gridbar();
    // P3: enc = softmax(G1) @ attrs (bf16)
    softmax_phase(attrs, smx);
    gridbar();
    // P4: q = enc @ att_g (64x32 tiles, nch=8) -> bf16
    {
        int bx = bid & 7, by = bid >> 3;
        gemm_small(g_enc_bf, g_gT_bf, g_q_bf, HD, AD, 8, by * 64, bx * 32, smh);
    }
    gridbar();
    // P5: G2 = q @ q^T, fused diag rsqrt
    {
        int bx = bid & 15, by = bid >> 4;
        gemm_phase(g_q_bf, g_q_bf, g_G, CP, HD, 4, by * 128, bx * 64, 1, smh);
    }
}

// -------- final fused softmax + proto-gather + SpMM (fp32 out) ---------------
__global__ __launch_bounds__(256) void softmax_spmm_final_k(const float* __restrict__ G,
                                                            const int* __restrict__ tpl,
                                                            float* __restrict__ Cc,
                                                            int mstore) {
    __shared__ float sh[32];
    __shared__ int scols[CP];
    __shared__ float svals[CP];
    __shared__ int cnt;
    int r = blockIdx.x;
    int t = threadIdx.x;
    if (r >= mstore) return;
    const float* gr = G + (size_t)r * CP;
    float ir = g_invn[r];
    float v[4];
    float mx = -1e30f;
#pragma unroll
    for (int j = 0; j < 4; j++) {
        int c = t + j * 256;
        float x = (c < C_CLS) ? gr[c] * ir * g_invn[c] : -1e30f;
        v[j] = x;
        if (x > 0.5f) mx = fmaxf(mx, x);
    }
    mx = blockMax(mx, sh);
    float m10 = mx * 10.f;
    float e[4];
    float s = 0.f;
#pragma unroll
    for (int j = 0; j < 4; j++) {
        e[j] = (v[j] > 0.5f) ? expf(v[j] * 10.f - m10) : 0.f;
        s += e[j];
    }
    s = blockSum(s, sh);
    float inv = 1.f / s;
    if (t == 0) cnt = 0;
    __syncthreads();
#pragma unroll
    for (int j = 0; j < 4; j++) {
        if (e[j] > 0.f) {
            int slot = atomicAdd(&cnt, 1);
            scols[slot] = t + j * 256;
            svals[slot] = e[j] * inv;
        }
    }
    __syncthreads();
    int n = cnt;
    float2 acc = make_float2(0.f, 0.f);
    for (int k = 0; k < n; k++) {
        int c = scols[k];
        int pc = tpl[c];
        int cc = g_counts[pc];
        float w = svals[k] * (cc > 0 ? 1.f / (float)cc : 0.f);
        float2 b0 = ((const float2*)(g_meanp + (size_t)(4 * pc + 0) * AD))[t];
        float2 b1 = ((const float2*)(g_meanp + (size_t)(4 * pc + 1) * AD))[t];
        float2 b2 = ((const float2*)(g_meanp + (size_t)(4 * pc + 2) * AD))[t];
        float2 b3 = ((const float2*)(g_meanp + (size_t)(4 * pc + 3) * AD))[t];
        acc.x += w * (b0.x + b1.x + b2.x + b3.x);
        acc.y += w * (b0.y + b1.y + b2.y + b3.y);
    }
    ((float2*)Cc)[(size_t)r * (AD / 2) + t] = acc;
}

// ---------------- launch ------------------------------------------------------
extern "C" void kernel_launch(void* const* d_in, const int* in_sizes, int n_in,
                              void* d_out, int out_size) {
    const float* img    = (const float*)d_in[0];
    const float* attrs  = (const float*)d_in[1];
    const float* att_g  = (const float*)d_in[2];
    const float* att_h  = (const float*)d_in[3];
    const int*   labels = (const int*)d_in[4];
    const int*   tpl    = (const int*)d_in[5];
    float* out = (float*)d_out;
    int N = in_sizes[4];
    (void)n_in; (void)out_size;

    cudaFuncSetAttribute(mega_k, cudaFuncAttributeMaxDynamicSharedMemorySize, GSMEM);

    void *p_G, *p_counts, *p_cursor;
    cudaGetSymbolAddress(&p_G, g_G);
    cudaGetSymbolAddress(&p_counts, g_counts);
    cudaGetSymbolAddress(&p_cursor, g_cursor);

    int prLo, prHi;
    cudaDeviceGetStreamPriorityRange(&prLo, &prHi);
    cudaStream_t s1;
    cudaStreamCreateWithPriority(&s1, cudaStreamNonBlocking, prHi);
    cudaEvent_t evF, evJ;
    cudaEventCreateWithFlags(&evF, cudaEventDisableTiming);
    cudaEventCreateWithFlags(&evJ, cudaEventDisableTiming);

    cudaEventRecord(evF, 0);
    cudaStreamWaitEvent(s1, evF, 0);

    // --- high-priority side stream: sort + class partial sums ---
    cudaMemsetAsync(p_counts, 0, C_CLS * sizeof(int), s1);
    cudaMemsetAsync(p_cursor, 0, C_CLS * sizeof(int), s1);
    hist_scan_k<<<HIST_BLOCKS, 256, 0, s1>>>(labels, N);
    scatter_k<<<(N + 1023) / 1024, 256, 0, s1>>>(labels, N);
    class_mean4_k<<<4 * C_CLS, 256, 0, s1>>>(img);
    cudaEventRecord(evJ, s1);

    // --- main stream: megakernel (P0..P5, 5 grid barriers) ---
    mega_k<<<GRID_MAIN, 256, GSMEM>>>(attrs, att_h, att_g);

    // join, final fused softmax + proto gather + SpMM
    cudaStreamWaitEvent(0, evJ, 0);
    softmax_spmm_final_k<<<C_CLS, 256>>>((float*)p_G, tpl, out, C_CLS);
}